// round 2
// baseline (speedup 1.0000x reference)
#include <cuda_runtime.h>
#include <math.h>

#define N_ROWS 100000
#define NF 50
#define NB 16
#define NK 15
#define FPC 1e-4

// ---------------- device scratch (no allocation allowed) -------------------
__device__ unsigned g_comp32[(size_t)N_ROWS * NF / 2];       // 10 MB: 16-bit masks, 2 per word
__device__ unsigned long long g_pack_bad[NF * 4];            // 16-bit packed counters, 4 bins/word
__device__ unsigned long long g_pack_good[NF * 4];
__device__ int   g_n1;
__device__ float g_wuse[NF * NB];

// ---------------------------------------------------------------------------
__global__ void zero_kernel() {
    int t = threadIdx.x;
    if (t < NF * 4) { g_pack_bad[t] = 0ull; g_pack_good[t] = 0ull; }
    if (t == 0) g_n1 = 0;
}

// ---------------------------------------------------------------------------
// K1: pure streaming compress. Each thread handles 2 (n,f) pairs -> 1 uint.
#define CP_THREADS 256
__global__ void __launch_bounds__(CP_THREADS)
compress_kernel(const float* __restrict__ x) {
    unsigned idx = blockIdx.x * CP_THREADS + threadIdx.x;
    const unsigned TOTAL = (unsigned)(N_ROWS * NF / 2);   // 2,500,000
    if (idx >= TOTAL) return;

    const float4* xp = (const float4*)x + (size_t)idx * 8;
    unsigned m = 0;
    #pragma unroll
    for (int j = 0; j < 8; j++) {
        float4 v = xp[j];
        m |= (v.x != 0.f) << (j * 4 + 0);
        m |= (v.y != 0.f) << (j * 4 + 1);
        m |= (v.z != 0.f) << (j * 4 + 2);
        m |= (v.w != 0.f) << (j * 4 + 3);
    }
    g_comp32[idx] = m;
}

// ---------------------------------------------------------------------------
// K2: counts from compressed masks. blockDim = 800 = 16 r-slots x 50 features.
// Thread (r, f) owns feature f permanently -> packed register counters.
#define CNT_THREADS 800
#define CNT_RPB 800                      // rows per block
#define CNT_BLOCKS (N_ROWS / CNT_RPB)    // 125
#define CNT_ITERS (CNT_RPB / 16)         // 50 masks per thread

__device__ __forceinline__ unsigned long long nib_spread(unsigned v) {
    // bit k of v (k<4) -> bit 16k of result
    return ((unsigned long long)v * 0x0000200040008001ULL) & 0x0001000100010001ULL;
}

__global__ void __launch_bounds__(CNT_THREADS)
count_kernel(const int* __restrict__ y) {
    __shared__ int sh_y[CNT_RPB];
    const int tid = threadIdx.x;
    const int r = tid / NF;
    const int f = tid % NF;
    const int baseRow = blockIdx.x * CNT_RPB;

    for (int j = tid; j < CNT_RPB; j += CNT_THREADS) sh_y[j] = y[baseRow + j];
    __syncthreads();

    const unsigned short* comp = (const unsigned short*)g_comp32;
    const size_t base = (size_t)baseRow * NF;

    unsigned long long ab0 = 0, ab1 = 0, ab2 = 0, ab3 = 0;
    unsigned long long ag0 = 0, ag1 = 0, ag2 = 0, ag3 = 0;

    #pragma unroll 4
    for (int i = 0; i < CNT_ITERS; i++) {
        unsigned m = comp[base + (size_t)i * CNT_THREADS + tid];
        int bad = sh_y[i * 16 + r];
        unsigned long long s0 = nib_spread(m & 15u);
        unsigned long long s1 = nib_spread((m >> 4) & 15u);
        unsigned long long s2 = nib_spread((m >> 8) & 15u);
        unsigned long long s3 = nib_spread(m >> 12);
        if (bad) { ab0 += s0; ab1 += s1; ab2 += s2; ab3 += s3; }
        else     { ag0 += s0; ag1 += s1; ag2 += s2; ag3 += s3; }
    }

    atomicAdd(&g_pack_bad[f * 4 + 0], ab0);
    atomicAdd(&g_pack_bad[f * 4 + 1], ab1);
    atomicAdd(&g_pack_bad[f * 4 + 2], ab2);
    atomicAdd(&g_pack_bad[f * 4 + 3], ab3);
    atomicAdd(&g_pack_good[f * 4 + 0], ag0);
    atomicAdd(&g_pack_good[f * 4 + 1], ag1);
    atomicAdd(&g_pack_good[f * 4 + 2], ag2);
    atomicAdd(&g_pack_good[f * 4 + 3], ag3);

    // n1: warp 0 sums this block's y tile
    if (tid < 32) {
        int c = 0;
        for (int j = tid; j < CNT_RPB; j += 32) c += sh_y[j];
        #pragma unroll
        for (int s = 16; s > 0; s >>= 1) c += __shfl_xor_sync(0xffffffffu, c, s);
        if (tid == 0) atomicAdd(&g_n1, c);
    }
}

// ---------------------------------------------------------------------------
// K3: tiny WLS, one thread per feature, double precision.
__global__ void wls_kernel(float* __restrict__ out) {
    int f = threadIdx.x;
    if (f >= NF) return;

    const int n1 = g_n1;
    const int n0 = N_ROWS - n1;

    double woe[NB], tot[NB];
    #pragma unroll
    for (int b = 0; b < NB; b++) {
        int cb = (int)((g_pack_bad [f * 4 + (b >> 2)] >> (16 * (b & 3))) & 0xFFFF);
        int cg = (int)((g_pack_good[f * 4 + (b >> 2)] >> (16 * (b & 3))) & 0xFFFF);
        woe[b] = log((double)cb / (double)n1 + FPC) - log((double)cg / (double)n0 + FPC);
        tot[b] = (double)(cb + cg) / (double)N_ROWS;
    }

    double s = 0.0;
    for (int k = 0; k < NK; k++) s += tot[k + 1];
    double pct[NK], w[NK];
    for (int k = 0; k < NK; k++) { pct[k] = tot[k + 1] / s; w[k] = woe[k + 1]; }

    int first = 0;
    for (int k = 0; k < NK; k++) { if (pct[k] != 0.0) { first = k; break; } }

    double idxv[NK], ind[NK];
    for (int k = 0; k < NK; k++) {
        double v = (double)(k + 1 - first);
        if (v < 0.0) v = 0.0;
        idxv[k] = v;
        ind[k]  = (v != 0.0) ? 1.0 : 0.0;
    }

    // Fit 1: X = [ind, idx]
    double s00 = 0, s01 = 0, s11 = 0, r0 = 0, r1v = 0;
    for (int k = 0; k < NK; k++) {
        double p = pct[k], u = ind[k], v = idxv[k];
        s00 += p * u * u; s01 += p * u * v; s11 += p * v * v;
        r0 += p * u * w[k]; r1v += p * v * w[k];
    }
    double det2 = s00 * s11 - s01 * s01;
    double c10 = (s11 * r0 - s01 * r1v) / det2;
    double c11 = (s00 * r1v - s01 * r0) / det2;
    double fit1[NK];
    for (int k = 0; k < NK; k++) fit1[k] = ind[k] * c10 + idxv[k] * c11;

    // Fit 2: X = [ind, idx, idx^2]
    double a00 = 0, a01 = 0, a02 = 0, a11 = 0, a12 = 0, a22 = 0;
    double b0 = 0, b1 = 0, b2 = 0;
    for (int k = 0; k < NK; k++) {
        double p = pct[k], u = ind[k], v = idxv[k], v2 = v * v;
        a00 += p * u * u; a01 += p * u * v; a02 += p * u * v2;
        a11 += p * v * v; a12 += p * v * v2; a22 += p * v2 * v2;
        b0 += p * u * w[k]; b1 += p * v * w[k]; b2 += p * v2 * w[k];
    }
    double det3 = a00 * (a11 * a22 - a12 * a12)
                - a01 * (a01 * a22 - a12 * a02)
                + a02 * (a01 * a12 - a11 * a02);
    double c20 = (b0 * (a11 * a22 - a12 * a12)
                - a01 * (b1 * a22 - a12 * b2)
                + a02 * (b1 * a12 - a11 * b2)) / det3;
    double c21 = (a00 * (b1 * a22 - a12 * b2)
                - b0 * (a01 * a22 - a12 * a02)
                + a02 * (a01 * b2 - b1 * a02)) / det3;
    double c22 = (a00 * (a11 * b2 - b1 * a12)
                - a01 * (a01 * b2 - b1 * a02)
                + b0 * (a01 * a12 - a11 * a02)) / det3;
    double fit2[NK];
    for (int k = 0; k < NK; k++)
        fit2[k] = ind[k] * c20 + idxv[k] * c21 + idxv[k] * idxv[k] * c22;

    double mean = 0;
    for (int k = 0; k < NK; k++) mean += w[k] * pct[k];
    double sst = 0, sse1 = 0, sse2 = 0;
    for (int k = 0; k < NK; k++) {
        double d = w[k] - mean; sst += d * d * pct[k];
        d = fit1[k] - w[k]; sse1 += d * d * pct[k];
        d = fit2[k] - w[k]; sse2 += d * d * pct[k];
    }
    double r1 = 1.0 - sse1 / sst;
    double r2 = 1.0 - sse2 / sst;

    float* out_woe = out + (size_t)N_ROWS * NF;   // 5,000,000
    float* out_adj = out_woe + NF * NB;           // +800

    #pragma unroll
    for (int b = 0; b < NB; b++) out_woe[f * NB + b] = (float)woe[b];

    float a0 = (float)woe[0];
    out_adj[f * NB + 0] = a0;
    g_wuse[f * NB + 0] = isnan(a0) ? 0.0f : a0;
    for (int k = 0; k < NK; k++) {
        double a = (fit1[k] * r1 + fit2[k] * r2) / (r1 + r2);
        float af = (float)a;
        out_adj[f * NB + 1 + k] = af;
        g_wuse[f * NB + 1 + k] = isnan(af) ? 0.0f : af;
    }
}

// ---------------------------------------------------------------------------
// K4: rt from masks. Fixed-f-per-thread mapping; w_use in 16 registers;
// 16 predicated adds (4 partial sums) per mask; fully coalesced I/O.
#define RT_THREADS 800
#define RT_RPB 400
#define RT_BLOCKS (N_ROWS / RT_RPB)      // 250
#define RT_ITERS (RT_RPB / 16)           // 25 masks per thread

__global__ void __launch_bounds__(RT_THREADS)
rt_kernel(float* __restrict__ out) {
    const int tid = threadIdx.x;
    const int f = tid % NF;
    const size_t base = (size_t)blockIdx.x * RT_RPB * NF;

    float wv[NB];
    #pragma unroll
    for (int b = 0; b < NB; b++) wv[b] = g_wuse[f * NB + b];

    const unsigned short* comp = (const unsigned short*)g_comp32;

    #pragma unroll 5
    for (int i = 0; i < RT_ITERS; i++) {
        size_t p = base + (size_t)i * RT_THREADS + tid;
        unsigned m = comp[p];
        float s0 = 0.f, s1 = 0.f, s2 = 0.f, s3 = 0.f;
        #pragma unroll
        for (int b = 0; b < NB; b += 4) {
            s0 += ((m >> (b + 0)) & 1u) ? wv[b + 0] : 0.f;
            s1 += ((m >> (b + 1)) & 1u) ? wv[b + 1] : 0.f;
            s2 += ((m >> (b + 2)) & 1u) ? wv[b + 2] : 0.f;
            s3 += ((m >> (b + 3)) & 1u) ? wv[b + 3] : 0.f;
        }
        out[p] = (s0 + s1) + (s2 + s3);
    }
}

// ---------------------------------------------------------------------------
extern "C" void kernel_launch(void* const* d_in, const int* in_sizes, int n_in,
                              void* d_out, int out_size) {
    const float* x = (const float*)d_in[0];
    const int* y = (const int*)d_in[1];
    float* out = (float*)d_out;

    zero_kernel<<<1, 256>>>();

    const unsigned TOTAL2 = (unsigned)(N_ROWS * NF / 2);
    compress_kernel<<<(TOTAL2 + CP_THREADS - 1) / CP_THREADS, CP_THREADS>>>(x);

    count_kernel<<<CNT_BLOCKS, CNT_THREADS>>>(y);

    wls_kernel<<<1, 64>>>(out);

    rt_kernel<<<RT_BLOCKS, RT_THREADS>>>(out);
}

// round 3
// speedup vs baseline: 1.3336x; 1.3336x over previous
#include <cuda_runtime.h>
#include <math.h>

#define N_ROWS 100000
#define NF 50
#define NB 16
#define NK 15
#define FPC 1e-4

// ---------------- device scratch (no allocation allowed) -------------------
__device__ unsigned g_comp32[(size_t)N_ROWS * NF / 2];       // 10 MB: 16-bit masks, 2 per word
__device__ unsigned long long g_pack_bad[NF * 4];            // 16-bit packed counters, 4 bins/word
__device__ unsigned long long g_pack_good[NF * 4];
__device__ int   g_n1;
__device__ float g_wuse[NF * NB];

// ---------------------------------------------------------------------------
// K1: pure streaming compress. Each thread handles 2 (n,f) pairs -> 1 uint.
// Block 0 also zeroes the packed counters (completes before count_kernel runs).
#define CP_THREADS 256
__global__ void __launch_bounds__(CP_THREADS)
compress_kernel(const float* __restrict__ x) {
    if (blockIdx.x == 0) {
        int t = threadIdx.x;
        if (t < NF * 4) { g_pack_bad[t] = 0ull; g_pack_good[t] = 0ull; }
        if (t == 0) g_n1 = 0;
    }

    unsigned idx = blockIdx.x * CP_THREADS + threadIdx.x;
    const unsigned TOTAL = (unsigned)(N_ROWS * NF / 2);   // 2,500,000
    if (idx >= TOTAL) return;

    const float4* xp = (const float4*)x + (size_t)idx * 8;
    unsigned m = 0;
    #pragma unroll
    for (int j = 0; j < 8; j++) {
        float4 v = xp[j];
        m |= (v.x != 0.f) << (j * 4 + 0);
        m |= (v.y != 0.f) << (j * 4 + 1);
        m |= (v.z != 0.f) << (j * 4 + 2);
        m |= (v.w != 0.f) << (j * 4 + 3);
    }
    g_comp32[idx] = m;
}

// ---------------------------------------------------------------------------
// K2: counts from compressed masks. blockDim = 800 = 16 r-slots x 50 features.
// Thread (r, f) owns feature f permanently -> packed register counters.
#define CNT_THREADS 800
#define CNT_RPB 800                      // rows per block
#define CNT_BLOCKS (N_ROWS / CNT_RPB)    // 125
#define CNT_ITERS (CNT_RPB / 16)         // 50 masks per thread

__device__ __forceinline__ unsigned long long nib_spread(unsigned v) {
    // bit k of v (k<4) -> bit 16k of result
    return ((unsigned long long)v * 0x0000200040008001ULL) & 0x0001000100010001ULL;
}

__global__ void __launch_bounds__(CNT_THREADS)
count_kernel(const int* __restrict__ y) {
    __shared__ int sh_y[CNT_RPB];
    const int tid = threadIdx.x;
    const int r = tid / NF;
    const int f = tid % NF;
    const int baseRow = blockIdx.x * CNT_RPB;

    for (int j = tid; j < CNT_RPB; j += CNT_THREADS) sh_y[j] = y[baseRow + j];
    __syncthreads();

    const unsigned short* comp = (const unsigned short*)g_comp32;
    const size_t base = (size_t)baseRow * NF;

    unsigned long long ab0 = 0, ab1 = 0, ab2 = 0, ab3 = 0;
    unsigned long long ag0 = 0, ag1 = 0, ag2 = 0, ag3 = 0;

    #pragma unroll 4
    for (int i = 0; i < CNT_ITERS; i++) {
        unsigned m = comp[base + (size_t)i * CNT_THREADS + tid];
        int bad = sh_y[i * 16 + r];
        unsigned long long s0 = nib_spread(m & 15u);
        unsigned long long s1 = nib_spread((m >> 4) & 15u);
        unsigned long long s2 = nib_spread((m >> 8) & 15u);
        unsigned long long s3 = nib_spread(m >> 12);
        if (bad) { ab0 += s0; ab1 += s1; ab2 += s2; ab3 += s3; }
        else     { ag0 += s0; ag1 += s1; ag2 += s2; ag3 += s3; }
    }

    atomicAdd(&g_pack_bad[f * 4 + 0], ab0);
    atomicAdd(&g_pack_bad[f * 4 + 1], ab1);
    atomicAdd(&g_pack_bad[f * 4 + 2], ab2);
    atomicAdd(&g_pack_bad[f * 4 + 3], ab3);
    atomicAdd(&g_pack_good[f * 4 + 0], ag0);
    atomicAdd(&g_pack_good[f * 4 + 1], ag1);
    atomicAdd(&g_pack_good[f * 4 + 2], ag2);
    atomicAdd(&g_pack_good[f * 4 + 3], ag3);

    // n1: warp 0 sums this block's y tile
    if (tid < 32) {
        int c = 0;
        for (int j = tid; j < CNT_RPB; j += 32) c += sh_y[j];
        #pragma unroll
        for (int s = 16; s > 0; s >>= 1) c += __shfl_xor_sync(0xffffffffu, c, s);
        if (tid == 0) atomicAdd(&g_n1, c);
    }
}

// ---------------------------------------------------------------------------
// K3: tiny WLS, one thread per feature. Logs in fp32 (matches the f32
// reference and avoids the 100µs fp64-log serial wall); solves in fp64.
__global__ void wls_kernel(float* __restrict__ out) {
    int f = threadIdx.x;
    if (f >= NF) return;

    const int n1 = g_n1;
    const int n0 = N_ROWS - n1;
    const float fn1 = (float)n1;
    const float fn0 = (float)n0;

    float woe[NB];
    double tot[NB];
    #pragma unroll
    for (int b = 0; b < NB; b++) {
        int cb = (int)((g_pack_bad [f * 4 + (b >> 2)] >> (16 * (b & 3))) & 0xFFFF);
        int cg = (int)((g_pack_good[f * 4 + (b >> 2)] >> (16 * (b & 3))) & 0xFFFF);
        float lb = logf((float)cb / fn1 + (float)FPC);
        float lg = logf((float)cg / fn0 + (float)FPC);
        woe[b] = lb - lg;
        tot[b] = (double)(cb + cg) / (double)N_ROWS;
    }

    double s = 0.0;
    for (int k = 0; k < NK; k++) s += tot[k + 1];
    double pct[NK], w[NK];
    for (int k = 0; k < NK; k++) { pct[k] = tot[k + 1] / s; w[k] = (double)woe[k + 1]; }

    int first = 0;
    for (int k = 0; k < NK; k++) { if (pct[k] != 0.0) { first = k; break; } }

    double idxv[NK], ind[NK];
    for (int k = 0; k < NK; k++) {
        double v = (double)(k + 1 - first);
        if (v < 0.0) v = 0.0;
        idxv[k] = v;
        ind[k]  = (v != 0.0) ? 1.0 : 0.0;
    }

    // Fit 1: X = [ind, idx]
    double s00 = 0, s01 = 0, s11 = 0, r0 = 0, r1v = 0;
    for (int k = 0; k < NK; k++) {
        double p = pct[k], u = ind[k], v = idxv[k];
        s00 += p * u * u; s01 += p * u * v; s11 += p * v * v;
        r0 += p * u * w[k]; r1v += p * v * w[k];
    }
    double det2 = s00 * s11 - s01 * s01;
    double c10 = (s11 * r0 - s01 * r1v) / det2;
    double c11 = (s00 * r1v - s01 * r0) / det2;
    double fit1[NK];
    for (int k = 0; k < NK; k++) fit1[k] = ind[k] * c10 + idxv[k] * c11;

    // Fit 2: X = [ind, idx, idx^2]
    double a00 = 0, a01 = 0, a02 = 0, a11 = 0, a12 = 0, a22 = 0;
    double b0 = 0, b1 = 0, b2 = 0;
    for (int k = 0; k < NK; k++) {
        double p = pct[k], u = ind[k], v = idxv[k], v2 = v * v;
        a00 += p * u * u; a01 += p * u * v; a02 += p * u * v2;
        a11 += p * v * v; a12 += p * v * v2; a22 += p * v2 * v2;
        b0 += p * u * w[k]; b1 += p * v * w[k]; b2 += p * v2 * w[k];
    }
    double det3 = a00 * (a11 * a22 - a12 * a12)
                - a01 * (a01 * a22 - a12 * a02)
                + a02 * (a01 * a12 - a11 * a02);
    double c20 = (b0 * (a11 * a22 - a12 * a12)
                - a01 * (b1 * a22 - a12 * b2)
                + a02 * (b1 * a12 - a11 * b2)) / det3;
    double c21 = (a00 * (b1 * a22 - a12 * b2)
                - b0 * (a01 * a22 - a12 * a02)
                + a02 * (a01 * b2 - b1 * a02)) / det3;
    double c22 = (a00 * (a11 * b2 - b1 * a12)
                - a01 * (a01 * b2 - b1 * a02)
                + b0 * (a01 * a12 - a11 * a02)) / det3;
    double fit2[NK];
    for (int k = 0; k < NK; k++)
        fit2[k] = ind[k] * c20 + idxv[k] * c21 + idxv[k] * idxv[k] * c22;

    double mean = 0;
    for (int k = 0; k < NK; k++) mean += w[k] * pct[k];
    double sst = 0, sse1 = 0, sse2 = 0;
    for (int k = 0; k < NK; k++) {
        double d = w[k] - mean; sst += d * d * pct[k];
        d = fit1[k] - w[k]; sse1 += d * d * pct[k];
        d = fit2[k] - w[k]; sse2 += d * d * pct[k];
    }
    double r1 = 1.0 - sse1 / sst;
    double r2 = 1.0 - sse2 / sst;

    float* out_woe = out + (size_t)N_ROWS * NF;   // 5,000,000
    float* out_adj = out_woe + NF * NB;           // +800

    #pragma unroll
    for (int b = 0; b < NB; b++) out_woe[f * NB + b] = woe[b];

    float a0 = woe[0];
    out_adj[f * NB + 0] = a0;
    g_wuse[f * NB + 0] = isnan(a0) ? 0.0f : a0;
    for (int k = 0; k < NK; k++) {
        double a = (fit1[k] * r1 + fit2[k] * r2) / (r1 + r2);
        float af = (float)a;
        out_adj[f * NB + 1 + k] = af;
        g_wuse[f * NB + 1 + k] = isnan(af) ? 0.0f : af;
    }
}

// ---------------------------------------------------------------------------
// K4: rt from masks. Fixed-f-per-thread mapping; w_use in 16 registers;
// 16 predicated adds (4 partial sums) per mask; fully coalesced I/O.
#define RT_THREADS 800
#define RT_RPB 400
#define RT_BLOCKS (N_ROWS / RT_RPB)      // 250
#define RT_ITERS (RT_RPB / 16)           // 25 masks per thread

__global__ void __launch_bounds__(RT_THREADS)
rt_kernel(float* __restrict__ out) {
    const int tid = threadIdx.x;
    const int f = tid % NF;
    const size_t base = (size_t)blockIdx.x * RT_RPB * NF;

    float wv[NB];
    #pragma unroll
    for (int b = 0; b < NB; b++) wv[b] = g_wuse[f * NB + b];

    const unsigned short* comp = (const unsigned short*)g_comp32;

    #pragma unroll 5
    for (int i = 0; i < RT_ITERS; i++) {
        size_t p = base + (size_t)i * RT_THREADS + tid;
        unsigned m = comp[p];
        float s0 = 0.f, s1 = 0.f, s2 = 0.f, s3 = 0.f;
        #pragma unroll
        for (int b = 0; b < NB; b += 4) {
            s0 += ((m >> (b + 0)) & 1u) ? wv[b + 0] : 0.f;
            s1 += ((m >> (b + 1)) & 1u) ? wv[b + 1] : 0.f;
            s2 += ((m >> (b + 2)) & 1u) ? wv[b + 2] : 0.f;
            s3 += ((m >> (b + 3)) & 1u) ? wv[b + 3] : 0.f;
        }
        out[p] = (s0 + s1) + (s2 + s3);
    }
}

// ---------------------------------------------------------------------------
extern "C" void kernel_launch(void* const* d_in, const int* in_sizes, int n_in,
                              void* d_out, int out_size) {
    const float* x = (const float*)d_in[0];
    const int* y = (const int*)d_in[1];
    float* out = (float*)d_out;

    const unsigned TOTAL2 = (unsigned)(N_ROWS * NF / 2);
    compress_kernel<<<(TOTAL2 + CP_THREADS - 1) / CP_THREADS, CP_THREADS>>>(x);

    count_kernel<<<CNT_BLOCKS, CNT_THREADS>>>(y);

    wls_kernel<<<1, 64>>>(out);

    rt_kernel<<<RT_BLOCKS, RT_THREADS>>>(out);
}

// round 4
// speedup vs baseline: 1.5746x; 1.1807x over previous
#include <cuda_runtime.h>
#include <math.h>

#define N_ROWS 100000
#define NF 50
#define NB 16
#define NK 15
#define FPC 1e-4

// ---------------- device scratch (no allocation allowed) -------------------
__device__ unsigned g_comp32[(size_t)N_ROWS * NF / 2];       // 10 MB: 16-bit masks, 2 per word
__device__ unsigned long long g_pack_bad[NF * 4];            // 16-bit packed counters, 4 bins/word
__device__ unsigned long long g_pack_good[NF * 4];
__device__ int   g_n1;
__device__ float g_wuse[NF * NB];

// ---------------------------------------------------------------------------
// K1: compress via warp-coalesced loads + ballots. One warp per row per pass:
// lane reads row[i*32+lane] (1 line per LDG), ballot IS the mask word.
// Word layout identical to (n*50+2i)/2 linear masks: word n*25+i covers
// floats [n*800+i*32, +32).
#define CP_RPW 16                               // rows per warp
#define CP_BLOCK 256
#define CP_WPB (CP_BLOCK / 32)                  // 8 warps/block
#define CP_BLOCKS ((N_ROWS + CP_RPW * CP_WPB - 1) / (CP_RPW * CP_WPB))

__global__ void __launch_bounds__(CP_BLOCK)
compress_kernel(const float* __restrict__ x) {
    if (blockIdx.x == 0) {
        int t = threadIdx.x;
        if (t < NF * 4) { g_pack_bad[t] = 0ull; g_pack_good[t] = 0ull; }
        if (t == 0) g_n1 = 0;
    }

    const int warp = (blockIdx.x * CP_BLOCK + threadIdx.x) >> 5;
    const int lane = threadIdx.x & 31;
    const int nbase = warp * CP_RPW;

    for (int r = 0; r < CP_RPW; r++) {
        int n = nbase + r;
        if (n >= N_ROWS) return;
        const float* row = x + (size_t)n * (NF * NB);
        unsigned myword = 0;
        #pragma unroll
        for (int i = 0; i < 25; i++) {
            float v = row[i * 32 + lane];
            unsigned b = __ballot_sync(0xffffffffu, v != 0.f);
            if (lane == i) myword = b;
        }
        if (lane < 25) g_comp32[(size_t)n * 25 + lane] = myword;
    }
}

// ---------------------------------------------------------------------------
// K2: counts from compressed masks. blockDim = 800 = 16 r-slots x 50 features.
// Thread (r, f) owns feature f permanently -> packed register counters.
#define CNT_THREADS 800
#define CNT_RPB 800
#define CNT_BLOCKS (N_ROWS / CNT_RPB)    // 125
#define CNT_ITERS (CNT_RPB / 16)         // 50 masks per thread

__device__ __forceinline__ unsigned long long nib_spread(unsigned v) {
    return ((unsigned long long)v * 0x0000200040008001ULL) & 0x0001000100010001ULL;
}

__global__ void __launch_bounds__(CNT_THREADS)
count_kernel(const int* __restrict__ y) {
    __shared__ int sh_y[CNT_RPB];
    const int tid = threadIdx.x;
    const int r = tid / NF;
    const int f = tid % NF;
    const int baseRow = blockIdx.x * CNT_RPB;

    for (int j = tid; j < CNT_RPB; j += CNT_THREADS) sh_y[j] = y[baseRow + j];
    __syncthreads();

    const unsigned short* comp = (const unsigned short*)g_comp32;
    const size_t base = (size_t)baseRow * NF;

    unsigned long long ab0 = 0, ab1 = 0, ab2 = 0, ab3 = 0;
    unsigned long long ag0 = 0, ag1 = 0, ag2 = 0, ag3 = 0;

    #pragma unroll 5
    for (int i = 0; i < CNT_ITERS; i++) {
        unsigned m = comp[base + (size_t)i * CNT_THREADS + tid];
        int bad = sh_y[i * 16 + r];
        unsigned long long s0 = nib_spread(m & 15u);
        unsigned long long s1 = nib_spread((m >> 4) & 15u);
        unsigned long long s2 = nib_spread((m >> 8) & 15u);
        unsigned long long s3 = nib_spread(m >> 12);
        if (bad) { ab0 += s0; ab1 += s1; ab2 += s2; ab3 += s3; }
        else     { ag0 += s0; ag1 += s1; ag2 += s2; ag3 += s3; }
    }

    atomicAdd(&g_pack_bad[f * 4 + 0], ab0);
    atomicAdd(&g_pack_bad[f * 4 + 1], ab1);
    atomicAdd(&g_pack_bad[f * 4 + 2], ab2);
    atomicAdd(&g_pack_bad[f * 4 + 3], ab3);
    atomicAdd(&g_pack_good[f * 4 + 0], ag0);
    atomicAdd(&g_pack_good[f * 4 + 1], ag1);
    atomicAdd(&g_pack_good[f * 4 + 2], ag2);
    atomicAdd(&g_pack_good[f * 4 + 3], ag3);

    if (tid < 32) {
        int c = 0;
        for (int j = tid; j < CNT_RPB; j += 32) c += sh_y[j];
        #pragma unroll
        for (int s = 16; s > 0; s >>= 1) c += __shfl_xor_sync(0xffffffffu, c, s);
        if (tid == 0) atomicAdd(&g_n1, c);
    }
}

// ---------------------------------------------------------------------------
// K3: WLS — one warp per feature. 15-element reductions become 4-stage
// shfl_xor butterflies; solves computed redundantly on all lanes.
__device__ __forceinline__ double red16(double v) {
    #pragma unroll
    for (int o = 8; o > 0; o >>= 1) v += __shfl_xor_sync(0xffffffffu, v, o);
    return v;
}

__global__ void wls_kernel(float* __restrict__ out) {
    const int f = blockIdx.x;
    const int lane = threadIdx.x;   // 32 lanes

    const int n1 = g_n1;
    const int n0 = N_ROWS - n1;

    // lane b<16: bin b counts + woe + tot
    float woe_b = 0.f;
    double tot_b = 0.0;
    if (lane < NB) {
        int cb = (int)((g_pack_bad [f * 4 + (lane >> 2)] >> (16 * (lane & 3))) & 0xFFFF);
        int cg = (int)((g_pack_good[f * 4 + (lane >> 2)] >> (16 * (lane & 3))) & 0xFFFF);
        woe_b = logf((float)cb / (float)n1 + (float)FPC)
              - logf((float)cg / (float)n0 + (float)FPC);
        tot_b = (double)(cb + cg) / (double)N_ROWS;
    }

    // k-space lives on lanes 1..15 (k = lane-1, bin = lane)
    const bool inK = (lane >= 1 && lane < NB);
    double s = red16(inK ? tot_b : 0.0);
    double pct = inK ? tot_b / s : 0.0;
    double w   = inK ? (double)woe_b : 0.0;

    // first nonzero pct (k-index); 0 if none
    unsigned nzmask = __ballot_sync(0xffffffffu, inK && pct != 0.0);
    int first = nzmask ? (__ffs(nzmask) - 2) : 0;   // lane L -> k = L-1

    double idxv = 0.0, ind = 0.0;
    if (inK) {
        double v = (double)(lane - first);          // k+1 - first
        idxv = v > 0.0 ? v : 0.0;
        ind  = (idxv != 0.0) ? 1.0 : 0.0;
    }
    double idx2 = idxv * idxv;

    // Fit 1: X = [ind, idx]
    double s00 = red16(pct * ind * ind);
    double s01 = red16(pct * ind * idxv);
    double s11 = red16(pct * idxv * idxv);
    double r0  = red16(pct * ind * w);
    double r1v = red16(pct * idxv * w);
    double det2 = s00 * s11 - s01 * s01;
    double c10 = (s11 * r0 - s01 * r1v) / det2;
    double c11 = (s00 * r1v - s01 * r0) / det2;
    double fit1 = ind * c10 + idxv * c11;

    // Fit 2: X = [ind, idx, idx^2]
    double a00 = s00;
    double a01 = s01;
    double a02 = red16(pct * ind * idx2);
    double a11 = s11;
    double a12 = red16(pct * idxv * idx2);
    double a22 = red16(pct * idx2 * idx2);
    double b0 = r0;
    double b1 = r1v;
    double b2 = red16(pct * idx2 * w);
    double m00 = a11 * a22 - a12 * a12;
    double m01 = a01 * a22 - a12 * a02;
    double m02 = a01 * a12 - a11 * a02;
    double det3 = a00 * m00 - a01 * m01 + a02 * m02;
    double c20 = (b0 * m00 - a01 * (b1 * a22 - a12 * b2) + a02 * (b1 * a12 - a11 * b2)) / det3;
    double c21 = (a00 * (b1 * a22 - a12 * b2) - b0 * m01 + a02 * (a01 * b2 - b1 * a02)) / det3;
    double c22 = (a00 * (a11 * b2 - b1 * a12) - a01 * (a01 * b2 - b1 * a02) + b0 * m02) / det3;
    double fit2 = ind * c20 + idxv * c21 + idx2 * c22;

    // R^2 + blend
    double mean = red16(w * pct);
    double d0 = w - mean;
    double d1 = fit1 - w;
    double d2 = fit2 - w;
    double sst  = red16(inK ? d0 * d0 * pct : 0.0);
    double sse1 = red16(inK ? d1 * d1 * pct : 0.0);
    double sse2 = red16(inK ? d2 * d2 * pct : 0.0);
    double r1 = 1.0 - sse1 / sst;
    double r2 = 1.0 - sse2 / sst;

    float* out_woe = out + (size_t)N_ROWS * NF;   // 5,000,000
    float* out_adj = out_woe + NF * NB;           // +800

    if (lane < NB) {
        out_woe[f * NB + lane] = woe_b;
        float a;
        if (lane == 0) {
            a = woe_b;                             // adj[:,0] = woe[:,0]
        } else {
            a = (float)((fit1 * r1 + fit2 * r2) / (r1 + r2));
        }
        out_adj[f * NB + lane] = a;
        g_wuse[f * NB + lane] = isnan(a) ? 0.0f : a;
    }
}

// ---------------------------------------------------------------------------
// K4: rt from masks. Fixed-f-per-thread mapping; w_use in 16 registers;
// 16 predicated adds (4 partial sums) per mask; fully coalesced I/O.
#define RT_THREADS 800
#define RT_RPB 160
#define RT_BLOCKS (N_ROWS / RT_RPB)      // 625
#define RT_ITERS (RT_RPB / 16)           // 10 masks per thread

__global__ void __launch_bounds__(RT_THREADS)
rt_kernel(float* __restrict__ out) {
    const int tid = threadIdx.x;
    const int f = tid % NF;
    const size_t base = (size_t)blockIdx.x * RT_RPB * NF;

    float wv[NB];
    #pragma unroll
    for (int b = 0; b < NB; b++) wv[b] = g_wuse[f * NB + b];

    const unsigned short* comp = (const unsigned short*)g_comp32;

    #pragma unroll
    for (int i = 0; i < RT_ITERS; i++) {
        size_t p = base + (size_t)i * RT_THREADS + tid;
        unsigned m = comp[p];
        float s0 = 0.f, s1 = 0.f, s2 = 0.f, s3 = 0.f;
        #pragma unroll
        for (int b = 0; b < NB; b += 4) {
            s0 += ((m >> (b + 0)) & 1u) ? wv[b + 0] : 0.f;
            s1 += ((m >> (b + 1)) & 1u) ? wv[b + 1] : 0.f;
            s2 += ((m >> (b + 2)) & 1u) ? wv[b + 2] : 0.f;
            s3 += ((m >> (b + 3)) & 1u) ? wv[b + 3] : 0.f;
        }
        out[p] = (s0 + s1) + (s2 + s3);
    }
}

// ---------------------------------------------------------------------------
extern "C" void kernel_launch(void* const* d_in, const int* in_sizes, int n_in,
                              void* d_out, int out_size) {
    const float* x = (const float*)d_in[0];
    const int* y = (const int*)d_in[1];
    float* out = (float*)d_out;

    compress_kernel<<<CP_BLOCKS, CP_BLOCK>>>(x);

    count_kernel<<<CNT_BLOCKS, CNT_THREADS>>>(y);

    wls_kernel<<<NF, 32>>>(out);

    rt_kernel<<<RT_BLOCKS, RT_THREADS>>>(out);
}